// round 11
// baseline (speedup 1.0000x reference)
#include <cuda_runtime.h>
#include <cuda_bf16.h>

#define NG 10000
#define W 256
#define H 256
#define TSX 32
#define TSY 16
#define TX 8           // tiles per row (32px wide)
#define TY 16          // tile rows (16px tall)
#define SEGS 8
#define SEGN (NG / SEGS)   // 1250
#define CAP  SEGN
#define ZSPLIT 4
#define NTILE (TX * TY)    // 128

// Static device scratch (all zero-init; reset in-kernel for graph replay)
static __device__ float4 g_parA[NG];                    // cx, cy, ha*log2e, b*log2e
static __device__ float4 g_parB[NG];                    // hc*log2e, log2(op), colR, colG
static __device__ float  g_parC[NG];                    // colB
static __device__ int    g_tlist[NTILE * SEGS * CAP];
static __device__ int    g_tcnt[NTILE * SEGS];
static __device__ float  g_part[ZSPLIT][3 * H * W];
static __device__ int    g_done[NTILE];
static __device__ int    g_segbar[SEGS];
static __device__ int    g_flag[TY * SEGS];
static __device__ int    g_tiles;

__device__ __forceinline__ float fast_tanh(float x) {
    float e;
    asm("ex2.approx.f32 %0, %1;" : "=f"(e) : "f"(x * 2.885390081777927f)); // 2*log2e
    float r;
    asm("rcp.approx.f32 %0, %1;" : "=f"(r) : "f"(1.0f + e));
    return 1.0f - 2.0f * r;
}

__global__ __launch_bounds__(256, 4) void fused_kernel(
    const float* __restrict__ xyz,
    const float* __restrict__ chol,
    const float* __restrict__ colors,
    const float* __restrict__ opacity,
    const float* __restrict__ scale_f,
    const float* __restrict__ shift_f,
    float* __restrict__ out) {
    __shared__ float4 sA[256];
    __shared__ float4 sB[256];
    __shared__ float  sC[256];
    __shared__ unsigned sball[TX][9];
    __shared__ int sbase[TX];
    __shared__ int sLast;

    const int tid = threadIdx.x, lane = tid & 31, wid = tid >> 5;
    const int bx = blockIdx.x, row = blockIdx.y, z = blockIdx.z;
    const bool isProducer = (z == 0);   // 128 producer blocks: seg = bx? need 8 segs x 16 rows
    // producer mapping: blocks with z==0 (bx in 0..7, row in 0..15) -> (row, seg=bx)

    // ================= Producer: prep slice + seg barrier + bin ===============
    if (isProducer) {
        const int seg = bx;
        const int segBase = seg * SEGN;
        // --- prep: this block preps slice [segBase + row*79, +79) of its seg ---
        {
            int i0 = segBase + row * 79;
            int i = i0 + tid;
            if (tid < 79 && i < segBase + SEGN) {
                const float LOG2E = 1.4426950408889634f;
                float cx = 0.5f * W * (fast_tanh(xyz[2 * i]) + 1.0f);
                float cy = 0.5f * H * (fast_tanh(xyz[2 * i + 1]) + 1.0f);
                float L0 = chol[3 * i] + 0.5f;
                float L1 = chol[3 * i + 1];
                float L2 = chol[3 * i + 2] + 0.5f;
                float cxx = L0 * L0;
                float cxy = L0 * L1;
                float cyy = L1 * L1 + L2 * L2;
                float det = cxx * cyy - cxy * cxy;
                float inv = 1.0f / det;
                float op = opacity[i];
                float T = __logf(255.0f * op) + 0.05f;
                g_parA[i] = make_float4(cx, cy, 0.5f * cyy * inv * LOG2E, -cxy * inv * LOG2E);
                g_parB[i] = make_float4(0.5f * cxx * inv * LOG2E, __log2f(op),
                                        colors[3 * i], colors[3 * i + 1]);
                g_parC[i] = colors[3 * i + 2];
            }
        }
        // --- 16-block per-seg barrier (producers of this seg only) ---
        __threadfence();
        __syncthreads();
        if (tid == 0) {
            atomicAdd(&g_segbar[seg], 1);
            volatile int* vb = &g_segbar[seg];
            while (*vb < TY) __nanosleep(32);
        }
        __syncthreads();
        __threadfence();

        // --- bin this (row, seg): deterministic gid-ordered scatter ---
        const unsigned lmask = (1u << lane) - 1u;
        if (tid < TX) sbase[tid] = 0;
        __syncthreads();
        for (int it = 0; it < (SEGN + 255) / 256; it++) {
            int i = segBase + it * 256 + tid;
            bool inR = (i < segBase + SEGN);
            float4 A = inR ? g_parA[i] : make_float4(0, 0, 0, 0);
            float4 B = inR ? g_parB[i] : make_float4(0, 0, 0, 0);
            // recompute bbox from params: radius from T = log(255*op)+margin
            bool pass = false;
            int t0 = 0, t1 = 0;
            if (inR) {
                // ha = 0.5*cyy*inv*LOG2E ; recover radii via cov terms is lost.
                // Instead recompute from original inputs (cheap, 5 chunks only):
                float L0 = chol[3 * i] + 0.5f;
                float L1 = chol[3 * i + 1];
                float L2 = chol[3 * i + 2] + 0.5f;
                float cxx = L0 * L0;
                float cxy = L0 * L1;
                float cyy = L1 * L1 + L2 * L2;
                float det = cxx * cyy - cxy * cxy;
                float op = opacity[i];
                float T = __logf(255.0f * op) + 0.05f;
                if (det > 0.0f && op > 0.0f && T > 0.0f) {
                    float rx = sqrtf(2.0f * T * cxx) + 1.0f;
                    float ry = sqrtf(2.0f * T * cyy) + 1.0f;
                    float xlo = A.x - rx, xhi = A.x + rx;
                    float ylo = A.y - ry, yhi = A.y + ry;
                    if (xhi >= 0.0f && xlo <= (float)(W - 1) &&
                        yhi >= 0.0f && ylo <= (float)(H - 1)) {
                        int ty0 = max(0, (int)floorf(ylo * (1.0f / TSY)));
                        int ty1 = min(TY - 1, (int)floorf(yhi * (1.0f / TSY)));
                        if (ty0 <= row && row <= ty1) {
                            t0 = max(0, (int)floorf(xlo * (1.0f / TSX)));
                            t1 = min(TX - 1, (int)floorf(xhi * (1.0f / TSX)));
                            pass = true;
                        }
                    }
                }
            }
            #pragma unroll
            for (int tx = 0; tx < TX; tx++) {
                unsigned b = __ballot_sync(0xffffffffu, pass && (t0 <= tx) && (tx <= t1));
                if (lane == 0) sball[tx][wid] = b;
            }
            __syncthreads();
            if (pass) {
                for (int tx = t0; tx <= t1; tx++) {
                    int pos = sbase[tx];
                    #pragma unroll
                    for (int k = 0; k < 8; k++)
                        if (k < wid) pos += __popc(sball[tx][k]);
                    pos += __popc(sball[tx][wid] & lmask);
                    g_tlist[((row * TX + tx) * SEGS + seg) * CAP + pos] = i;
                }
            }
            __syncthreads();
            if (tid < TX) {
                int s = 0;
                #pragma unroll
                for (int k = 0; k < 8; k++) s += __popc(sball[tid][k]);
                sbase[tid] += s;
            }
            __syncthreads();
        }
        if (tid < TX) g_tcnt[(row * TX + tid) * SEGS + seg] = sbase[tid];
        // publish
        __threadfence();
        __syncthreads();
        if (tid == 0) atomicExch(&g_flag[row * SEGS + seg], 1);
    }

    // ================= Consumer: wait for this tile-z's two seg lists =========
    const int seg0 = z * (SEGS / ZSPLIT);
    if (tid == 0) {
        volatile int* f0 = &g_flag[row * SEGS + seg0];
        volatile int* f1 = &g_flag[row * SEGS + seg0 + 1];
        while (*f0 == 0) __nanosleep(64);
        while (*f1 == 0) __nanosleep(64);
    }
    __syncthreads();
    __threadfence();

    // ================= Render: 2 px per thread (px, px+16) ====================
    const int lx = tid & 15, ly = tid >> 4;
    const int px = bx * TSX + lx, py = row * TSY + ly;
    const float fpx = (float)px, fpy = (float)py;
    const int tileIdx = row * TX + bx;

    float aR1 = 0.f, aG1 = 0.f, aB1 = 0.f;
    float aR2 = 0.f, aG2 = 0.f, aB2 = 0.f;

    for (int s = 0; s < SEGS / ZSPLIT; s++) {
        const int seg = seg0 + s;
        const int cnt = g_tcnt[tileIdx * SEGS + seg];
        const int* lst = g_tlist + (tileIdx * SEGS + seg) * CAP;
        for (int base = 0; base < cnt; base += 256) {
            int i = base + tid;
            if (i < cnt) {
                int g = lst[i];
                sA[tid] = g_parA[g];
                sB[tid] = g_parB[g];
                sC[tid] = g_parC[g];
            }
            __syncthreads();
            int m = min(256, cnt - base);
            #pragma unroll 2
            for (int j = 0; j < m; j++) {
                float4 A = sA[j];
                float4 B = sB[j];
                float dy  = A.y - fpy;
                float dx1 = A.x - fpx;
                float dx2 = dx1 - 16.0f;
                float cdyy = (B.x * dy) * dy;   // hc*dy^2 (shared)
                float bdy  = A.w * dy;          // b*dy (shared)
                float sig1 = fmaf(A.z * dx1, dx1, fmaf(bdy, dx1, cdyy));
                float sig2 = fmaf(A.z * dx2, dx2, fmaf(bdy, dx2, cdyy));
                float al1, al2;
                asm("ex2.approx.f32 %0, %1;" : "=f"(al1) : "f"(B.y - sig1));
                asm("ex2.approx.f32 %0, %1;" : "=f"(al2) : "f"(B.y - sig2));
                float w1 = ((sig1 >= 0.0f) && (al1 >= (1.0f / 255.0f)))
                               ? fminf(al1, 0.999f) : 0.0f;
                float w2 = ((sig2 >= 0.0f) && (al2 >= (1.0f / 255.0f)))
                               ? fminf(al2, 0.999f) : 0.0f;
                aR1 = fmaf(w1, B.z, aR1);  aR2 = fmaf(w2, B.z, aR2);
                aG1 = fmaf(w1, B.w, aG1);  aG2 = fmaf(w2, B.w, aG2);
                aB1 = fmaf(w1, sC[j], aB1); aB2 = fmaf(w2, sC[j], aB2);
            }
            __syncthreads();
        }
    }

    const int idx = py * W + px;   // second pixel at idx+16
    g_part[z][0 * (H * W) + idx] = aR1;  g_part[z][0 * (H * W) + idx + 16] = aR2;
    g_part[z][1 * (H * W) + idx] = aG1;  g_part[z][1 * (H * W) + idx + 16] = aG2;
    g_part[z][2 * (H * W) + idx] = aB1;  g_part[z][2 * (H * W) + idx + 16] = aB2;

    // ---- elect last z for this tile; reduce 4 partials in fixed order ----
    __threadfence();
    __syncthreads();
    if (tid == 0) sLast = atomicAdd(&g_done[tileIdx], 1);
    __syncthreads();
    if (sLast != ZSPLIT - 1) return;

    __threadfence();
    float sc = scale_f[0], sh = shift_f[0];
    #pragma unroll
    for (int c = 0; c < 3; c++) {
        int o = c * (H * W) + idx;
        float v1 = ((g_part[0][o] + g_part[1][o]) + (g_part[2][o] + g_part[3][o]));
        out[o] = fmaf(v1, sc, sh);
        int o2 = o + 16;
        float v2 = ((g_part[0][o2] + g_part[1][o2]) + (g_part[2][o2] + g_part[3][o2]));
        out[o2] = fmaf(v2, sc, sh);
    }

    // ---- last tile overall resets all coordination state for next replay ----
    __threadfence();
    __syncthreads();
    if (tid == 0) sLast = atomicAdd(&g_tiles, 1);
    __syncthreads();
    if (sLast == NTILE - 1) {
        if (tid < NTILE) g_done[tid] = 0;
        if (tid < TY * SEGS) g_flag[tid] = 0;
        if (tid < SEGS) g_segbar[tid] = 0;
        if (tid == 0) g_tiles = 0;
        __threadfence();
    }
}

extern "C" void kernel_launch(void* const* d_in, const int* in_sizes, int n_in,
                              void* d_out, int out_size) {
    const float* xyz     = (const float*)d_in[0];
    const float* chol    = (const float*)d_in[1];
    const float* colors  = (const float*)d_in[2];
    const float* opacity = (const float*)d_in[3];
    const float* scale_f = (const float*)d_in[4];
    const float* shift_f = (const float*)d_in[5];
    float* out = (float*)d_out;

    fused_kernel<<<dim3(TX, TY, ZSPLIT), 256>>>(xyz, chol, colors, opacity,
                                                scale_f, shift_f, out);
}

// round 12
// speedup vs baseline: 1.0702x; 1.0702x over previous
#include <cuda_runtime.h>
#include <cuda_bf16.h>

#define NG 10000
#define W 256
#define H 256
#define TSX 32
#define TSY 16
#define TX 8               // tiles per row (32 px wide)
#define TY 16              // tile rows (16 px tall)
#define NTILE (TX * TY)    // 128
#define SEGS 8
#define SEGN (NG / SEGS)   // 1250
#define CAP  SEGN
#define ZSPLIT 8           // one segment per z

// Static device scratch (no dynamic allocation anywhere)
static __device__ float4 g_parA[NG];                    // cx, cy, ha*log2e, b*log2e
static __device__ float4 g_parB[NG];                    // hc*log2e, log2(op), colR, colG
static __device__ float  g_parC[NG];                    // colB
static __device__ int    g_rng[NG];                     // tx0|tx1<<4|ty0<<8|ty1<<12
static __device__ float4 g_eAB[NTILE * SEGS * CAP * 2]; // embedded entries (A,B)
static __device__ float  g_eC[NTILE * SEGS * CAP];      // embedded colB
static __device__ int    g_tcnt[NTILE * SEGS];
static __device__ float  g_part[ZSPLIT][3 * H * W];
static __device__ int    g_done[NTILE];

__device__ __forceinline__ float fast_tanh(float x) {
    float e;
    asm("ex2.approx.f32 %0, %1;" : "=f"(e) : "f"(x * 2.885390081777927f)); // 2*log2e
    float r;
    asm("rcp.approx.f32 %0, %1;" : "=f"(r) : "f"(1.0f + e));
    return 1.0f - 2.0f * r;
}

// Prep: params + tile ranges; also resets per-tile counters (runs first in-stream).
__global__ __launch_bounds__(256) void prep_kernel(
    const float* __restrict__ xyz,
    const float* __restrict__ chol,
    const float* __restrict__ colors,
    const float* __restrict__ opacity) {
    int i = blockIdx.x * 256 + threadIdx.x;
    if (i < NTILE) g_done[i] = 0;
    if (i >= NG) return;
    const float LOG2E = 1.4426950408889634f;
    float cx = 0.5f * W * (fast_tanh(__ldg(xyz + 2 * i)) + 1.0f);
    float cy = 0.5f * H * (fast_tanh(__ldg(xyz + 2 * i + 1)) + 1.0f);
    float L0 = __ldg(chol + 3 * i) + 0.5f;
    float L1 = __ldg(chol + 3 * i + 1);
    float L2 = __ldg(chol + 3 * i + 2) + 0.5f;
    float cxx = L0 * L0;
    float cxy = L0 * L1;
    float cyy = L1 * L1 + L2 * L2;
    float det = cxx * cyy - cxy * cxy;
    float inv = 1.0f / det;
    float op = __ldg(opacity + i);
    float T = __logf(255.0f * op) + 0.05f;

    int tx0 = 15, tx1 = 0, ty0 = 15, ty1 = 0;  // empty
    if (det > 0.0f && op > 0.0f && T > 0.0f) {
        float rx = sqrtf(2.0f * T * cxx) + 1.0f;
        float ry = sqrtf(2.0f * T * cyy) + 1.0f;
        float xlo = cx - rx, xhi = cx + rx;
        float ylo = cy - ry, yhi = cy + ry;
        if (xhi >= 0.0f && xlo <= (float)(W - 1) &&
            yhi >= 0.0f && ylo <= (float)(H - 1)) {
            tx0 = max(0, (int)floorf(xlo * (1.0f / TSX)));
            tx1 = min(TX - 1, (int)floorf(xhi * (1.0f / TSX)));
            ty0 = max(0, (int)floorf(ylo * (1.0f / TSY)));
            ty1 = min(TY - 1, (int)floorf(yhi * (1.0f / TSY)));
        }
    }
    g_rng[i]  = tx0 | (tx1 << 4) | (ty0 << 8) | (ty1 << 12);
    g_parA[i] = make_float4(cx, cy, 0.5f * cyy * inv * LOG2E, -cxy * inv * LOG2E);
    g_parB[i] = make_float4(0.5f * cxx * inv * LOG2E, __log2f(op),
                            __ldg(colors + 3 * i), __ldg(colors + 3 * i + 1));
    g_parC[i] = __ldg(colors + 3 * i + 2);
}

// Binning: grid (SEGS, TY). Deterministic gid-ordered scatter of EMBEDDED
// entries into the row's 8 per-tile lists.
__global__ __launch_bounds__(256) void bin_kernel() {
    const int seg = blockIdx.x, row = blockIdx.y;
    const int tid = threadIdx.x, lane = tid & 31, wid = tid >> 5;
    __shared__ unsigned sball[TX][9];
    __shared__ int sbase[TX];
    const int segBase = seg * SEGN;
    const unsigned lmask = (1u << lane) - 1u;

    if (tid < TX) sbase[tid] = 0;
    __syncthreads();

    for (int it = 0; it < (SEGN + 255) / 256; it++) {
        int i = segBase + it * 256 + tid;
        int rng = (i < segBase + SEGN) ? g_rng[i] : 0x0F00;
        int ty0 = (rng >> 8) & 15, ty1 = (rng >> 12) & 15;
        int t0 = rng & 15, t1 = (rng >> 4) & 15;
        bool pass = (ty0 <= row) && (row <= ty1);
        #pragma unroll
        for (int tx = 0; tx < TX; tx++) {
            unsigned b = __ballot_sync(0xffffffffu, pass && (t0 <= tx) && (tx <= t1));
            if (lane == 0) sball[tx][wid] = b;
        }
        __syncthreads();
        if (pass) {
            float4 pA = g_parA[i];
            float4 pB = g_parB[i];
            float  pC = g_parC[i];
            for (int tx = t0; tx <= t1; tx++) {
                int pos = sbase[tx];
                #pragma unroll
                for (int k = 0; k < 8; k++)
                    if (k < wid) pos += __popc(sball[tx][k]);
                pos += __popc(sball[tx][wid] & lmask);
                int o = ((row * TX + tx) * SEGS + seg) * CAP + pos;
                g_eAB[2 * o]     = pA;
                g_eAB[2 * o + 1] = pB;
                g_eC[o]          = pC;
            }
        }
        __syncthreads();
        if (tid < TX) {
            int s = 0;
            #pragma unroll
            for (int k = 0; k < 8; k++) s += __popc(sball[tid][k]);
            sbase[tid] += s;
        }
        __syncthreads();
    }
    if (tid < TX) g_tcnt[(row * TX + tid) * SEGS + seg] = sbase[tid];
}

// Render: grid (TX, TY, ZSPLIT); 2 px/thread; sync-free inner loop via uniform
// __ldg of embedded entries. Last-z block reduces 8 partials in fixed order.
__global__ __launch_bounds__(256) void render_kernel(
    const float* __restrict__ scale_f,
    const float* __restrict__ shift_f,
    float* __restrict__ out) {
    __shared__ int sLast;

    const int tid = threadIdx.x;
    const int bx = blockIdx.x, row = blockIdx.y, seg = blockIdx.z;
    const int px = bx * TSX + (tid & 15), py = row * TSY + (tid >> 4);
    const float fpx = (float)px, fpy = (float)py;
    const int tileIdx = row * TX + bx;

    const int cnt = g_tcnt[tileIdx * SEGS + seg];
    const float4* eAB = g_eAB + (tileIdx * SEGS + seg) * CAP * 2;
    const float*  eC  = g_eC  + (tileIdx * SEGS + seg) * CAP;

    float aR1 = 0.f, aG1 = 0.f, aB1 = 0.f;
    float aR2 = 0.f, aG2 = 0.f, aB2 = 0.f;

    #pragma unroll 4
    for (int j = 0; j < cnt; j++) {
        float4 A = __ldg(eAB + 2 * j);
        float4 B = __ldg(eAB + 2 * j + 1);
        float  C = __ldg(eC + j);
        float dy  = A.y - fpy;
        float dx1 = A.x - fpx;
        float dx2 = dx1 - 16.0f;
        float cdyy = (B.x * dy) * dy;   // hc*dy^2 (shared)
        float bdy  = A.w * dy;          // b*dy (shared)
        float k1 = B.y - fmaf(A.z * dx1, dx1, fmaf(bdy, dx1, cdyy));
        float k2 = B.y - fmaf(A.z * dx2, dx2, fmaf(bdy, dx2, cdyy));
        float al1, al2;
        asm("ex2.approx.f32 %0, %1;" : "=f"(al1) : "f"(k1));
        asm("ex2.approx.f32 %0, %1;" : "=f"(al2) : "f"(k2));
        float w1 = (al1 >= (1.0f / 255.0f)) ? fminf(al1, 0.999f) : 0.0f;
        float w2 = (al2 >= (1.0f / 255.0f)) ? fminf(al2, 0.999f) : 0.0f;
        aR1 = fmaf(w1, B.z, aR1);  aR2 = fmaf(w2, B.z, aR2);
        aG1 = fmaf(w1, B.w, aG1);  aG2 = fmaf(w2, B.w, aG2);
        aB1 = fmaf(w1, C,   aB1);  aB2 = fmaf(w2, C,   aB2);
    }

    const int idx = py * W + px;   // second pixel at idx+16
    g_part[seg][0 * (H * W) + idx] = aR1;  g_part[seg][0 * (H * W) + idx + 16] = aR2;
    g_part[seg][1 * (H * W) + idx] = aG1;  g_part[seg][1 * (H * W) + idx + 16] = aG2;
    g_part[seg][2 * (H * W) + idx] = aB1;  g_part[seg][2 * (H * W) + idx + 16] = aB2;

    // elect last z-block for this tile; reduce 8 partials in fixed order
    __threadfence();
    __syncthreads();
    if (tid == 0) sLast = atomicAdd(&g_done[tileIdx], 1);
    __syncthreads();
    if (sLast != ZSPLIT - 1) return;

    __threadfence();
    float sc = scale_f[0], sh = shift_f[0];
    #pragma unroll
    for (int c = 0; c < 3; c++) {
        #pragma unroll
        for (int p = 0; p < 2; p++) {
            int o = c * (H * W) + idx + p * 16;
            float v = ((g_part[0][o] + g_part[1][o]) + (g_part[2][o] + g_part[3][o]))
                    + ((g_part[4][o] + g_part[5][o]) + (g_part[6][o] + g_part[7][o]));
            out[o] = fmaf(v, sc, sh);
        }
    }
}

extern "C" void kernel_launch(void* const* d_in, const int* in_sizes, int n_in,
                              void* d_out, int out_size) {
    const float* xyz     = (const float*)d_in[0];
    const float* chol    = (const float*)d_in[1];
    const float* colors  = (const float*)d_in[2];
    const float* opacity = (const float*)d_in[3];
    const float* scale_f = (const float*)d_in[4];
    const float* shift_f = (const float*)d_in[5];
    float* out = (float*)d_out;

    prep_kernel<<<(NG + 255) / 256, 256>>>(xyz, chol, colors, opacity);
    bin_kernel<<<dim3(SEGS, TY), 256>>>();
    render_kernel<<<dim3(TX, TY, ZSPLIT), 256>>>(scale_f, shift_f, out);
}